// round 17
// baseline (speedup 1.0000x reference)
#include <cuda_runtime.h>

#define NCFG 128
#define VEC  16384
#define NB   8192
#define ETA  0.001f
#define NBLK 256

// Dynamic smem: vec[16384] + aux[1536]  (aux = staging in C, T+vbuf in D)
#define DYN_FLOATS (VEC + 1536)
#define DYN_BYTES  (DYN_FLOATS * 4)     // 71680 B; x2 blocks/SM = 140KB < 228KB

// Scratch (no allocation allowed)
__device__ float g_corr[NCFG * VEC];   // 8 MB: ETA * (H @ W2)
__device__ float g_h[NCFG * 64];       // NN hidden layer
__device__ unsigned g_cnt   = 0;
__device__ unsigned g_epoch = 0;

// Sense-free grid barrier: epoch monotonic across graph replays; count resets
// each pass. Safe: all NBLK=256 blocks co-resident (2 blocks/SM, 148 SMs).
__device__ __forceinline__ void grid_barrier() {
    __syncthreads();
    if (threadIdx.x == 0) {
        __threadfence();
        volatile unsigned* ep = &g_epoch;
        unsigned base = *ep;
        unsigned old = atomicAdd(&g_cnt, 1);
        if (old == NBLK - 1) {
            g_cnt = 0;
            __threadfence();
            atomicAdd(&g_epoch, 1);
        } else {
            while (*ep == base) __nanosleep(32);
        }
        __threadfence();
    }
    __syncthreads();
}

__global__ void __launch_bounds__(256, 2)
k_fused(const int* __restrict__ cfg,
        const float* __restrict__ A,
        const float* __restrict__ W1,
        const float* __restrict__ b1,
        const float* __restrict__ W2,
        const float* __restrict__ b2,
        float* __restrict__ out)
{
    extern __shared__ float dyn[];
    const int blk = blockIdx.x;
    const int tid = threadIdx.x;   // 256

    // ======== Step A: h[blk] = relu(cfg[blk] @ W1 + b1)  (blk < 128) =========
    if (blk < NCFG && tid < 64) {
        float acc = b1[tid];
        #pragma unroll
        for (int ii = 0; ii < 32; ii++)
            acc = fmaf((float)cfg[blk * 32 + ii], W1[ii * 64 + tid], acc);
        g_h[blk * 64 + tid] = fmaxf(acc, 0.f);
    }

    grid_barrier();   // protects g_h

    // ======== Step B: g_corr = ETA * (H @ W2), FFMA2 (pure stores) ===========
    // 512 col-tiles of 32 cols; each block does tiles blk and blk+256.
    {
        float (*sH)[66] = (float (*)[66])dyn;            // [128][66]
        float (*sW)[32] = (float (*)[32])(dyn + 128 * 66);

        for (int n = tid; n < 8192; n += 256)
            sH[n >> 6][n & 63] = g_h[n];

        #pragma unroll 1
        for (int t = blk; t < 512; t += NBLK) {
            const int colBase = t * 32;
            __syncthreads();
            for (int n = tid; n < 2048; n += 256)
                sW[n >> 5][n & 31] = W2[(n >> 5) * 16384 + colBase + (n & 31)];
            __syncthreads();

            const int rb = tid >> 3;   // rows rb*4 .. rb*4+3
            const int cb = tid & 7;    // cols cb*4 .. cb*4+3 (2 f32x2 pairs)

            unsigned long long acc[4][2];
            #pragma unroll
            for (int i = 0; i < 4; i++) { acc[i][0] = 0ull; acc[i][1] = 0ull; }

            #pragma unroll 8
            for (int k = 0; k < 64; k++) {
                unsigned long long h[4], w[2];
                #pragma unroll
                for (int i = 0; i < 4; i++) {
                    float hv = sH[rb * 4 + i][k];
                    asm("mov.b64 %0, {%1, %2};" : "=l"(h[i]) : "f"(hv), "f"(hv));
                }
                w[0] = *(const unsigned long long*)&sW[k][cb * 4 + 0];
                w[1] = *(const unsigned long long*)&sW[k][cb * 4 + 2];
                #pragma unroll
                for (int i = 0; i < 4; i++) {
                    asm("fma.rn.f32x2 %0, %1, %2, %0;" : "+l"(acc[i][0]) : "l"(h[i]), "l"(w[0]));
                    asm("fma.rn.f32x2 %0, %1, %2, %0;" : "+l"(acc[i][1]) : "l"(h[i]), "l"(w[1]));
                }
            }

            #pragma unroll
            for (int i = 0; i < 4; i++) {
                unsigned row = rb * 4 + i;
                #pragma unroll
                for (int j = 0; j < 2; j++) {
                    float2 v = *(float2*)&acc[i][j];
                    v.x *= ETA; v.y *= ETA;
                    *(float2*)&g_corr[row * VEC + colBase + cb * 4 + 2 * j] = v;
                }
            }
        }
    }

    grid_barrier();   // protects g_corr

    if (blk >= NCFG) return;   // idle blocks free their SMs for the chain

    // ======== Step C: full vec (base + eta*b2 + corr) into SMEM ==============
    float* vec = dyn;                  // [16384]
    float* stg = dyn + VEC;            // [1024] staging (aliases T/vbuf of D)
    const int b = blk;
    const float* corr = g_corr + b * VEC;

    #pragma unroll 1
    for (int x = 0; x < 8; x++) {
        __syncthreads();   // prior tile's staging reads / GEMM smem use done
        // gather: y == t since tid<256
        #pragma unroll
        for (int t = 0; t < 4; t++) {
            float2 a2 = ((const float2*)A)[(x * 4 + t) * 256 + tid];
            int p = cfg[b * 32 + x * 4 + t];
            stg[t * 256 + tid] = p ? a2.y : a2.x;
        }
        __syncthreads();

        const int n0 = tid * 4;
        const int i = n0 >> 6, j = (n0 >> 2) & 15;
        const int l = i >> 2, L = i & 3, r = j >> 2, R = j & 3;

        // bot quad: bot[i,j,U] = sum_u s0[l,r,u] * s1[L,R,u*4+U]
        {
            float4 acc = make_float4(0.f, 0.f, 0.f, 0.f);
            #pragma unroll
            for (int u = 0; u < 4; u++) {
                float a = stg[0 * 256 + l * 64 + r * 16 + u];
                float4 w = *(const float4*)&stg[1 * 256 + L * 64 + R * 16 + u * 4];
                acc.x = fmaf(a, w.x, acc.x); acc.y = fmaf(a, w.y, acc.y);
                acc.z = fmaf(a, w.z, acc.z); acc.w = fmaf(a, w.w, acc.w);
            }
            float4 bb = *(const float4*)&b2[x * 1024 + n0];
            float4 cc = *(const float4*)&corr[x * 1024 + n0];
            acc.x = fmaf(ETA, bb.x, acc.x) + cc.x;
            acc.y = fmaf(ETA, bb.y, acc.y) + cc.y;
            acc.z = fmaf(ETA, bb.z, acc.z) + cc.z;
            acc.w = fmaf(ETA, bb.w, acc.w) + cc.w;
            *(float4*)&vec[x * 1024 + n0] = acc;
        }
        // top quad: top[i,j,d] = sum_u s2[l,r,d*4+u] * s3[L,R,u*4]
        {
            float w0 = stg[3 * 256 + L * 64 + R * 16 + 0];
            float w1 = stg[3 * 256 + L * 64 + R * 16 + 4];
            float w2 = stg[3 * 256 + L * 64 + R * 16 + 8];
            float w3 = stg[3 * 256 + L * 64 + R * 16 + 12];
            float4 acc;
            #pragma unroll
            for (int d = 0; d < 4; d++) {
                float4 v = *(const float4*)&stg[2 * 256 + l * 64 + r * 16 + d * 4];
                ((float*)&acc)[d] = fmaf(v.x, w0, fmaf(v.y, w1, fmaf(v.z, w2, v.w * w3)));
            }
            float4 bb = *(const float4*)&b2[NB + x * 1024 + n0];
            float4 cc = *(const float4*)&corr[NB + x * 1024 + n0];
            acc.x = fmaf(ETA, bb.x, acc.x) + cc.x;
            acc.y = fmaf(ETA, bb.y, acc.y) + cc.y;
            acc.z = fmaf(ETA, bb.z, acc.z) + cc.z;
            acc.w = fmaf(ETA, bb.w, acc.w) + cc.w;
            *(float4*)&vec[NB + x * 1024 + n0] = acc;
        }
    }

    // ======== Step D: chain directly out of smem vec =========================
    float* T    = dyn + VEC;          // [1024] (staging reads done after sync)
    float* vbuf = dyn + VEC + 1024;   // [2][256]

    __syncthreads();                  // vec complete; stg reads done
    vbuf[tid] = (tid == 0) ? 1.f : 0.f;   // vbuf[0][tid]

    int cur = 0;
    #pragma unroll 1
    for (int x = 0; x < 8; x++) {
        const float* sbot = vec + x * 1024;
        const float* stop = vec + NB + x * 1024;
        __syncthreads();   // vbuf[cur] ready (also covers init & T reuse)

        // T[i,J,u] quad
        {
            const int n0 = tid * 4;
            const int i = n0 >> 6, J = (n0 >> 2) & 15;
            float4 acc = make_float4(0.f, 0.f, 0.f, 0.f);
            #pragma unroll
            for (int I = 0; I < 16; I++) {
                float vv = vbuf[cur * 256 + i * 16 + I];
                float4 tp = *(const float4*)&stop[I * 64 + J * 4];
                acc.x = fmaf(vv, tp.x, acc.x); acc.y = fmaf(vv, tp.y, acc.y);
                acc.z = fmaf(vv, tp.z, acc.z); acc.w = fmaf(vv, tp.w, acc.w);
            }
            *(float4*)&T[n0] = acc;
        }
        __syncthreads();

        // vnew[j,J]
        {
            const int j = tid >> 4, J = tid & 15;
            float acc = 0.f;
            #pragma unroll
            for (int i = 0; i < 16; i++) {
                float4 bo = *(const float4*)&sbot[i * 64 + j * 4];
                float4 tt = *(const float4*)&T[i * 64 + J * 4];
                acc = fmaf(bo.x, tt.x, acc);
                acc = fmaf(bo.y, tt.y, acc);
                acc = fmaf(bo.z, tt.z, acc);
                acc = fmaf(bo.w, tt.w, acc);
            }
            vbuf[(cur ^ 1) * 256 + tid] = acc;
        }
        cur ^= 1;
    }
    __syncthreads();
    if (tid == 0) out[b] = vbuf[cur * 256];
}

// ---------------------------------------------------------------------------
extern "C" void kernel_launch(void* const* d_in, const int* in_sizes, int n_in,
                              void* d_out, int out_size)
{
    const int*   cfg = (const int*)  d_in[0];
    const float* A   = (const float*)d_in[1];
    const float* W1  = (const float*)d_in[2];
    const float* b1  = (const float*)d_in[3];
    const float* W2  = (const float*)d_in[4];
    const float* b2  = (const float*)d_in[5];
    float* out = (float*)d_out;

    cudaFuncSetAttribute(k_fused, cudaFuncAttributeMaxDynamicSharedMemorySize,
                         DYN_BYTES);
    k_fused<<<NBLK, 256, DYN_BYTES>>>(cfg, A, W1, b1, W2, b2, out);
}